// round 16
// baseline (speedup 1.0000x reference)
#include <cuda_runtime.h>
#include <cuda_fp16.h>
#include <cstdint>
#include <math.h>

#define Dd    2048
#define NTOK  4096
#define Sq    1024
#define HDh   64
#define NBH   128
#define EPSV  1e-5f
#define INV_SQRT_D 0.022097086912079608f

// ---------------- scratch ---------------------------------------------------
__device__ float g_x2[(size_t)NTOK * Dd];
__device__ __half g_h [(size_t)NTOK * Dd];
__device__ __half g_h2[(size_t)NTOK * Dd];
__device__ __half g_f1[(size_t)NTOK * Dd];
__device__ __half g_q[(size_t)NTOK * Dd], g_k[(size_t)NTOK * Dd];
__device__ __half g_wq[(size_t)Dd * Dd], g_wk[(size_t)Dd * Dd];
__device__ __half g_w1[(size_t)Dd * Dd], g_w2[(size_t)Dd * Dd];

// ---------------- helpers ----------------------------------------------------
__device__ __forceinline__ uint32_t smem_u32(const void* p) {
    return (uint32_t)__cvta_generic_to_shared(p);
}
__device__ __forceinline__ void cp16(uint32_t dst, const void* src) {
    asm volatile("cp.async.cg.shared.global [%0], [%1], 16;" :: "r"(dst), "l"(src));
}
__device__ __forceinline__ void cp_commit() {
    asm volatile("cp.async.commit_group;");
}
template<int N> __device__ __forceinline__ void cp_wait() {
    asm volatile("cp.async.wait_group %0;" :: "n"(N));
}
__device__ __forceinline__ void ldmx4(uint32_t a, uint32_t& r0, uint32_t& r1,
                                      uint32_t& r2, uint32_t& r3) {
    asm volatile("ldmatrix.sync.aligned.m8n8.x4.shared.b16 {%0,%1,%2,%3},[%4];"
                 : "=r"(r0), "=r"(r1), "=r"(r2), "=r"(r3) : "r"(a));
}
__device__ __forceinline__ void ldmx4t(uint32_t a, uint32_t& r0, uint32_t& r1,
                                       uint32_t& r2, uint32_t& r3) {
    asm volatile("ldmatrix.sync.aligned.m8n8.x4.trans.shared.b16 {%0,%1,%2,%3},[%4];"
                 : "=r"(r0), "=r"(r1), "=r"(r2), "=r"(r3) : "r"(a));
}
__device__ __forceinline__ void mma16816(float* c, const uint32_t* a, const uint32_t* b) {
    asm volatile(
        "mma.sync.aligned.m16n8k16.row.col.f32.f16.f16.f32 "
        "{%0,%1,%2,%3},{%4,%5,%6,%7},{%8,%9},{%0,%1,%2,%3};"
        : "+f"(c[0]), "+f"(c[1]), "+f"(c[2]), "+f"(c[3])
        : "r"(a[0]), "r"(a[1]), "r"(a[2]), "r"(a[3]), "r"(b[0]), "r"(b[1]));
}

// ---------------- all-weights convert (one launch) ----------------------------
struct CvtArgs {
    const float4* w[4];
    __half* o[4];
};
__global__ __launch_bounds__(256) void cvt_all(CvtArgs a, int n4) {
    const int z = blockIdx.y;
    const float4* W = a.w[z];
    __half* o = a.o[z];
    int i = blockIdx.x * 256 + threadIdx.x;
    if (i >= n4) return;
    float4 v = W[i];
    *(__half2*)(o + (size_t)i * 4)     = __floats2half2_rn(v.x, v.y);
    *(__half2*)(o + (size_t)i * 4 + 2) = __floats2half2_rn(v.z, v.w);
}

// ---------------- fused LN1 / residual / LN2 (single-plane fp16 outputs) ------
__global__ __launch_bounds__(256) void ln_fused(
    const float* __restrict__ x,
    const float* __restrict__ s1, const float* __restrict__ b1,
    const float* __restrict__ s2, const float* __restrict__ b2)
{
    __shared__ float rbuf[16];
    __shared__ float stats[2];
    const int tid = threadIdx.x;
    const size_t base = (size_t)blockIdx.x * Dd;
    const float4* xr = (const float4*)(x + base);
    float4 a0 = xr[tid];
    float4 a1 = xr[tid + 256];

    float s = a0.x + a0.y + a0.z + a0.w + a1.x + a1.y + a1.z + a1.w;
    float q = a0.x*a0.x + a0.y*a0.y + a0.z*a0.z + a0.w*a0.w
            + a1.x*a1.x + a1.y*a1.y + a1.z*a1.z + a1.w*a1.w;
    #pragma unroll
    for (int o = 16; o; o >>= 1) {
        s += __shfl_xor_sync(0xffffffffu, s, o);
        q += __shfl_xor_sync(0xffffffffu, q, o);
    }
    if ((tid & 31) == 0) { rbuf[tid >> 5] = s; rbuf[8 + (tid >> 5)] = q; }
    __syncthreads();
    if (tid == 0) {
        float ss = 0.f, qq = 0.f;
        #pragma unroll
        for (int i = 0; i < 8; i++) { ss += rbuf[i]; qq += rbuf[8 + i]; }
        float m = ss * (1.0f / Dd);
        stats[0] = m;
        stats[1] = rsqrtf(qq * (1.0f / Dd) - m * m + EPSV);
    }
    __syncthreads();
    float m = stats[0], r = stats[1];

    const float4* s1v = (const float4*)s1;
    const float4* b1v = (const float4*)b1;
    float4 sc0 = s1v[tid], sc1 = s1v[tid + 256];
    float4 bi0 = b1v[tid], bi1 = b1v[tid + 256];

    float4 h0, h1, x20, x21;
    h0.x = (a0.x - m) * r * sc0.x + bi0.x;  h0.y = (a0.y - m) * r * sc0.y + bi0.y;
    h0.z = (a0.z - m) * r * sc0.z + bi0.z;  h0.w = (a0.w - m) * r * sc0.w + bi0.w;
    h1.x = (a1.x - m) * r * sc1.x + bi1.x;  h1.y = (a1.y - m) * r * sc1.y + bi1.y;
    h1.z = (a1.z - m) * r * sc1.z + bi1.z;  h1.w = (a1.w - m) * r * sc1.w + bi1.w;
    x20.x = h0.x + a0.x; x20.y = h0.y + a0.y; x20.z = h0.z + a0.z; x20.w = h0.w + a0.w;
    x21.x = h1.x + a1.x; x21.y = h1.y + a1.y; x21.z = h1.z + a1.z; x21.w = h1.w + a1.w;

    *(__half2*)(g_h + base + (size_t)tid * 4)       = __floats2half2_rn(h0.x, h0.y);
    *(__half2*)(g_h + base + (size_t)tid * 4 + 2)   = __floats2half2_rn(h0.z, h0.w);
    *(__half2*)(g_h + base + (size_t)(tid + 256) * 4)     = __floats2half2_rn(h1.x, h1.y);
    *(__half2*)(g_h + base + (size_t)(tid + 256) * 4 + 2) = __floats2half2_rn(h1.z, h1.w);
    ((float4*)(g_x2 + base))[tid]       = x20;
    ((float4*)(g_x2 + base))[tid + 256] = x21;

    s = x20.x + x20.y + x20.z + x20.w + x21.x + x21.y + x21.z + x21.w;
    q = x20.x*x20.x + x20.y*x20.y + x20.z*x20.z + x20.w*x20.w
      + x21.x*x21.x + x21.y*x21.y + x21.z*x21.z + x21.w*x21.w;
    #pragma unroll
    for (int o = 16; o; o >>= 1) {
        s += __shfl_xor_sync(0xffffffffu, s, o);
        q += __shfl_xor_sync(0xffffffffu, q, o);
    }
    if ((tid & 31) == 0) { rbuf[tid >> 5] = s; rbuf[8 + (tid >> 5)] = q; }
    __syncthreads();
    if (tid == 0) {
        float ss = 0.f, qq = 0.f;
        #pragma unroll
        for (int i = 0; i < 8; i++) { ss += rbuf[i]; qq += rbuf[8 + i]; }
        float mm = ss * (1.0f / Dd);
        stats[0] = mm;
        stats[1] = rsqrtf(qq * (1.0f / Dd) - mm * mm + EPSV);
    }
    __syncthreads();
    m = stats[0]; r = stats[1];

    const float4* s2v = (const float4*)s2;
    const float4* b2v = (const float4*)b2;
    sc0 = s2v[tid]; sc1 = s2v[tid + 256];
    bi0 = b2v[tid]; bi1 = b2v[tid + 256];
    float4 o0, o1;
    o0.x = (x20.x - m) * r * sc0.x + bi0.x;  o0.y = (x20.y - m) * r * sc0.y + bi0.y;
    o0.z = (x20.z - m) * r * sc0.z + bi0.z;  o0.w = (x20.w - m) * r * sc0.w + bi0.w;
    o1.x = (x21.x - m) * r * sc1.x + bi1.x;  o1.y = (x21.y - m) * r * sc1.y + bi1.y;
    o1.z = (x21.z - m) * r * sc1.z + bi1.z;  o1.w = (x21.w - m) * r * sc1.w + bi1.w;
    *(__half2*)(g_h2 + base + (size_t)tid * 4)       = __floats2half2_rn(o0.x, o0.y);
    *(__half2*)(g_h2 + base + (size_t)tid * 4 + 2)   = __floats2half2_rn(o0.z, o0.w);
    *(__half2*)(g_h2 + base + (size_t)(tid + 256) * 4)     = __floats2half2_rn(o1.x, o1.y);
    *(__half2*)(g_h2 + base + (size_t)(tid + 256) * 4 + 2) = __floats2half2_rn(o1.z, o1.w);
}

// ---------------------------------------------------------------------------
// Pure fp16 GEMM, cp.async 3-stage ring, BK=64 (R15, kept).
// ---------------------------------------------------------------------------
#define GA_B     18432u
#define GA_STAGE 35840u
#define GA_SMEM  107520u
#define GA_ITERS (Dd / 64)

template<int EPI, bool DUAL>
__global__ __launch_bounds__(256, 2) void gemm_ca(
    const __half* __restrict__ Am,
    const __half* __restrict__ Bm, const __half* __restrict__ Bm2,
    float* __restrict__ C,
    const float* __restrict__ bias, const float* __restrict__ addm,
    __half* __restrict__ O, __half* __restrict__ O2)
{
    extern __shared__ __align__(16) char dsm[];
    const uint32_t sb = smem_u32(dsm);
    const int N = Dd, K = Dd;

    const __half* Bsel = Bm;
    __half* Osel = O;
    if (DUAL && blockIdx.z == 1) { Bsel = Bm2; Osel = O2; }

    const int tid = threadIdx.x;
    const int m0 = blockIdx.y * 128, n0 = blockIdx.x * 128;

    auto ISSUE = [&](int ch, int stage) {
        uint32_t st = sb + (uint32_t)stage * GA_STAGE;
        const int kof = ch * 64;
        #pragma unroll
        for (int p = 0; p < 4; p++) {
            int idx = tid + p * 256;
            int ar = idx >> 3, ac = (idx & 7) * 8;
            cp16(st + (uint32_t)(ar * 72 + ac) * 2,
                 Am + (size_t)(m0 + ar) * K + kof + ac);
            int br = idx >> 4, bc = (idx & 15) * 8;
            cp16(st + GA_B + (uint32_t)(br * 136 + bc) * 2,
                 Bsel + (size_t)(kof + br) * N + n0 + bc);
        }
        cp_commit();
    };

    const int lane = tid & 31;
    const int wid = tid >> 5;
    const int wm = (wid & 1) * 64;
    const int wn = (wid >> 1) * 32;
    const uint32_t aRow = (uint32_t)((wm + (lane & 15)) * 72 + ((lane >> 4) << 3)) * 2;
    const uint32_t bRow = (uint32_t)((lane & 15) * 136 + wn + ((lane >> 4) << 3)) * 2;

    float acc[4][4][4];
    #pragma unroll
    for (int i = 0; i < 4; i++)
        #pragma unroll
        for (int j = 0; j < 4; j++)
            #pragma unroll
            for (int t = 0; t < 4; t++) acc[i][j][t] = 0.f;

    auto COMP = [&](int stage) {
        const uint32_t aB = sb + (uint32_t)stage * GA_STAGE + aRow;
        const uint32_t bB = sb + (uint32_t)stage * GA_STAGE + GA_B + bRow;
        #pragma unroll
        for (int kb = 0; kb < 64; kb += 16) {
            uint32_t bf[4][2];
            #pragma unroll
            for (int np = 0; np < 2; np++) {
                ldmx4t(bB + ((kb * 136 + np * 16) << 1),
                       bf[2*np][0], bf[2*np][1], bf[2*np+1][0], bf[2*np+1][1]);
            }
            #pragma unroll
            for (int mt = 0; mt < 4; mt++) {
                uint32_t af[4];
                ldmx4(aB + ((mt * 16 * 72 + kb) << 1),
                      af[0], af[1], af[2], af[3]);
                #pragma unroll
                for (int nt = 0; nt < 4; nt++)
                    mma16816(acc[mt][nt], af, bf[nt]);
            }
        }
    };

    ISSUE(0, 0);
    ISSUE(1, 1);
    for (int it = 0; it < GA_ITERS; it++) {
        if (it == GA_ITERS - 1) cp_wait<0>(); else cp_wait<1>();
        __syncthreads();
        if (it + 2 < GA_ITERS) ISSUE(it + 2, (it + 2) % 3);
        COMP(it % 3);
    }

    const int g = lane >> 2, tig = lane & 3;
    #pragma unroll
    for (int mt = 0; mt < 4; mt++) {
        #pragma unroll
        for (int nt = 0; nt < 4; nt++) {
            const int row = m0 + wm + mt * 16 + g;
            const int col = n0 + wn + nt * 8 + tig * 2;
            const float* a4 = acc[mt][nt];
            if (EPI == 4) {
                *(__half2*)(Osel + (size_t)row * N + col) =
                    __floats2half2_rn(a4[0], a4[1]);
                *(__half2*)(Osel + (size_t)(row + 8) * N + col) =
                    __floats2half2_rn(a4[2], a4[3]);
            } else if (EPI == 1) {
                float b0 = bias[col], b1 = bias[col + 1];
                *(__half2*)(O + (size_t)row * N + col) =
                    __floats2half2_rn(fmaxf(a4[0] + b0, 0.f), fmaxf(a4[1] + b1, 0.f));
                *(__half2*)(O + (size_t)(row + 8) * N + col) =
                    __floats2half2_rn(fmaxf(a4[2] + b0, 0.f), fmaxf(a4[3] + b1, 0.f));
            } else { // EPI == 2
                float b0 = bias[col], b1 = bias[col + 1];
                float2 ad0 = *(const float2*)(addm + (size_t)row * N + col);
                float2 ad1 = *(const float2*)(addm + (size_t)(row + 8) * N + col);
                *(float2*)(C + (size_t)row * N + col) =
                    make_float2(a4[0] + b0 + ad0.x, a4[1] + b1 + ad0.y);
                *(float2*)(C + (size_t)(row + 8) * N + col) =
                    make_float2(a4[2] + b0 + ad1.x, a4[3] + b1 + ad1.y);
            }
        }
    }
}

// -----------------------------------------------------------------------------
// Fused scores + softmax — single-plane fp16 q/k (R11 WIN, unchanged).
// -----------------------------------------------------------------------------
#define FS_Q    0u
#define FS_K0   2304u
#define FS_KBUF 36864u
#define FS_RED  76032u
#define FS_SMEM 77056u

__global__ __launch_bounds__(512) void scores_softmax(
    const __half* __restrict__ Q, const __half* __restrict__ Kk,
    float* __restrict__ attn)
{
    extern __shared__ __align__(16) char dsm[];
    const uint32_t sbase = smem_u32(dsm);
    float* red = (float*)(dsm + FS_RED);

    const int tid = threadIdx.x;
    const int lane = tid & 31;
    const int wid = tid >> 5;
    const int bh = blockIdx.y;
    const int m0 = blockIdx.x * 16;
    const size_t off = (size_t)(bh >> 5) * ((size_t)Sq * Dd) + (size_t)(bh & 31) * HDh;

    if (tid < 128) {
        int row = tid >> 3, col = (tid & 7) * 8;
        cp16(sbase + FS_Q + (row * 72 + col) * 2,
             Q + off + (size_t)(m0 + row) * Dd + col);
    }
    auto ISSUEK = [&](int chunk, int buf) {
        #pragma unroll
        for (int p = 0; p < 4; p++) {
            int idx = tid + p * 512;
            int row = idx >> 3, col = (idx & 7) * 8;
            cp16(sbase + FS_K0 + (uint32_t)buf * FS_KBUF + (row * 72 + col) * 2,
                 Kk + off + (size_t)(chunk * 256 + row) * Dd + col);
        }
        cp_commit();
    };
    ISSUEK(0, 0);
    ISSUEK(1, 1);
    cp_wait<1>();
    __syncthreads();

    const uint32_t aOff = (((lane & 15)) * 72 + ((lane >> 4) << 3)) * 2;
    uint32_t af[4][4];
    #pragma unroll
    for (int kb4 = 0; kb4 < 4; kb4++) {
        ldmx4(sbase + FS_Q + aOff + ((kb4 * 16) << 1),
              af[kb4][0], af[kb4][1], af[kb4][2], af[kb4][3]);
    }

    const int bRow = ((lane >> 4) << 3) + (lane & 7);
    const int bKof = ((lane >> 3) & 1) << 3;
    const uint32_t bOff = ((wid * 16 + bRow) * 72 + bKof) * 2;

    float acc[4][2][4];
    #pragma unroll
    for (int it = 0; it < 4; it++)
        #pragma unroll
        for (int nt = 0; nt < 2; nt++)
            #pragma unroll
            for (int t = 0; t < 4; t++) acc[it][nt][t] = 0.f;

    #pragma unroll
    for (int it = 0; it < 4; it++) {
        const int buf = it & 1;
        const uint32_t kb = sbase + FS_K0 + (uint32_t)buf * FS_KBUF + bOff;
        #pragma unroll
        for (int kb4 = 0; kb4 < 4; kb4++) {
            uint32_t b4[4];
            ldmx4(kb + ((kb4 * 16) << 1), b4[0], b4[1], b4[2], b4[3]);
            mma16816(acc[it][0], af[kb4], &b4[0]);
            mma16816(acc[it][1], af[kb4], &b4[2]);
        }
        if (it < 2) {
            __syncthreads();
            ISSUEK(it + 2, buf);
            cp_wait<1>();
            __syncthreads();
        } else if (it == 2) {
            cp_wait<0>();
            __syncthreads();
        }
    }

    const int g = lane >> 2, tig = lane & 3;
    const float c = INV_SQRT_D;
    float mx0 = -1e30f, mx1 = -1e30f;
    #pragma unroll
    for (int it = 0; it < 4; it++)
        #pragma unroll
        for (int nt = 0; nt < 2; nt++) {
            float* a4 = acc[it][nt];
            a4[0] *= c; a4[1] *= c; a4[2] *= c; a4[3] *= c;
            mx0 = fmaxf(mx0, fmaxf(a4[0], a4[1]));
            mx1 = fmaxf(mx1, fmaxf(a4[2], a4[3]));
        }
    mx0 = fmaxf(mx0, __shfl_xor_sync(0xffffffffu, mx0, 1));
    mx0 = fmaxf(mx0, __shfl_xor_sync(0xffffffffu, mx0, 2));
    mx1 = fmaxf(mx1, __shfl_xor_sync(0xffffffffu, mx1, 1));
    mx1 = fmaxf(mx1, __shfl_xor_sync(0xffffffffu, mx1, 2));
    if (tig == 0) { red[g * 16 + wid] = mx0; red[(g + 8) * 16 + wid] = mx1; }
    __syncthreads();
    float m0f = -1e30f, m1f = -1e30f;
    #pragma unroll
    for (int w = 0; w < 16; w++) {
        m0f = fmaxf(m0f, red[g * 16 + w]);
        m1f = fmaxf(m1f, red[(g + 8) * 16 + w]);
    }
    __syncthreads();

    float s0 = 0.f, s1 = 0.f;
    #pragma unroll
    for (int it = 0; it < 4; it++)
        #pragma unroll
        for (int nt = 0; nt < 2; nt++) {
            float* a4 = acc[it][nt];
            a4[0] = __expf(a4[0] - m0f); a4[1] = __expf(a4[1] - m0f);
            a4[2] = __expf(a4[2] - m1f); a4[3] = __expf(a4[3] - m1f);
            s0 += a4[0] + a4[1];
            s1 += a4[2] + a4[3];
        }
    s0 += __shfl_xor_sync(0xffffffffu, s0, 1);
    s0 += __shfl_xor_sync(0xffffffffu, s0, 2);
    s1 += __shfl_xor_sync(0xffffffffu, s1, 1);
    s1 += __shfl_xor_sync(0xffffffffu, s1, 2);
    if (tig == 0) { red[g * 16 + wid] = s0; red[(g + 8) * 16 + wid] = s1; }
    __syncthreads();
    float t0 = 0.f, t1 = 0.f;
    #pragma unroll
    for (int w = 0; w < 16; w++) {
        t0 += red[g * 16 + w];
        t1 += red[(g + 8) * 16 + w];
    }
    const float inv0 = __fdividef(1.0f, t0);
    const float inv1 = __fdividef(1.0f, t1);

    float* base0 = attn + (size_t)bh * Sq * Sq + (size_t)(m0 + g) * Sq;
    float* base1 = base0 + (size_t)8 * Sq;
    #pragma unroll
    for (int it = 0; it < 4; it++)
        #pragma unroll
        for (int nt = 0; nt < 2; nt++) {
            const int col = it * 256 + wid * 16 + nt * 8 + tig * 2;
            const float* a4 = acc[it][nt];
            *(float2*)(base0 + col) = make_float2(a4[0] * inv0, a4[1] * inv0);
            *(float2*)(base1 + col) = make_float2(a4[2] * inv1, a4[3] * inv1);
        }
}

// -----------------------------------------------------------------------------
extern "C" void kernel_launch(void* const* d_in, const int* in_sizes, int n_in,
                              void* d_out, int out_size)
{
    (void)in_sizes; (void)n_in; (void)out_size;
    const float* x    = (const float*)d_in[0];
    const float* Wq   = (const float*)d_in[1];
    const float* Wk   = (const float*)d_in[2];
    /* d_in[3] = Wv : dead in the reference */
    const float* ln1s = (const float*)d_in[4];
    const float* ln1b = (const float*)d_in[5];
    const float* ln2s = (const float*)d_in[6];
    const float* ln2b = (const float*)d_in[7];
    const float* ff1w = (const float*)d_in[8];
    const float* ff1b = (const float*)d_in[9];
    const float* ff2w = (const float*)d_in[10];
    const float* ff2b = (const float*)d_in[11];

    float* out  = (float*)d_out;
    float* attn = out + (size_t)NTOK * Dd;

    float* px2;
    __half *ph, *ph2, *pf1, *pq, *pk;
    __half *pwq, *pwk, *pw1, *pw2;
    cudaGetSymbolAddress((void**)&px2, g_x2);
    cudaGetSymbolAddress((void**)&ph,  g_h);
    cudaGetSymbolAddress((void**)&ph2, g_h2);
    cudaGetSymbolAddress((void**)&pf1, g_f1);
    cudaGetSymbolAddress((void**)&pq,  g_q);
    cudaGetSymbolAddress((void**)&pk,  g_k);
    cudaGetSymbolAddress((void**)&pwq, g_wq);
    cudaGetSymbolAddress((void**)&pwk, g_wk);
    cudaGetSymbolAddress((void**)&pw1, g_w1);
    cudaGetSymbolAddress((void**)&pw2, g_w2);

    cudaFuncSetAttribute(gemm_ca<4, true>,
                         cudaFuncAttributeMaxDynamicSharedMemorySize, GA_SMEM);
    cudaFuncSetAttribute(gemm_ca<1, false>,
                         cudaFuncAttributeMaxDynamicSharedMemorySize, GA_SMEM);
    cudaFuncSetAttribute(gemm_ca<2, false>,
                         cudaFuncAttributeMaxDynamicSharedMemorySize, GA_SMEM);
    cudaFuncSetAttribute(scores_softmax,
                         cudaFuncAttributeMaxDynamicSharedMemorySize, FS_SMEM);

    // Side stream + fork/join events (host-side objects, created once).
    static cudaStream_t sB = nullptr;
    static cudaEvent_t evFork = nullptr, evJoin = nullptr;
    if (sB == nullptr) {
        int prLeast = 0, prGreatest = 0;
        cudaDeviceGetStreamPriorityRange(&prLeast, &prGreatest);
        cudaStreamCreateWithPriority(&sB, cudaStreamNonBlocking, prLeast);
        cudaEventCreateWithFlags(&evFork, cudaEventDisableTiming);
        cudaEventCreateWithFlags(&evJoin, cudaEventDisableTiming);
    }

    // --- stream 0: ln + cvt (shared prologue) ---
    ln_fused<<<NTOK, 256>>>(x, ln1s, ln1b, ln2s, ln2b);

    CvtArgs ca;
    ca.w[0] = (const float4*)Wq;   ca.o[0] = pwq;
    ca.w[1] = (const float4*)Wk;   ca.o[1] = pwk;
    ca.w[2] = (const float4*)ff1w; ca.o[2] = pw1;
    ca.w[3] = (const float4*)ff2w; ca.o[3] = pw2;
    const int n4 = Dd * Dd / 4;
    dim3 gc((n4 + 255) / 256, 4);
    cvt_all<<<gc, 256>>>(ca, n4);

    // --- stream 0: qk projection runs ALONE (tensor-bound, full chip) ---
    dim3 gqk(Dd / 128, NTOK / 128, 2);
    gemm_ca<4, true><<<gqk, 256, GA_SMEM>>>(ph, pwq, pwk,
                                            nullptr, nullptr, nullptr,
                                            pq, pk);

    // fork AFTER qk: FFN (tensor-bound) now overlaps scores (DRAM-bound),
    // pairing complementary bottlenecks instead of contending on tensor.
    cudaEventRecord(evFork, 0);
    cudaStreamWaitEvent(sB, evFork, 0);

    // --- chain A (stream 0): scores + softmax ---
    dim3 gs(Sq / 16, NBH);
    scores_softmax<<<gs, 512, FS_SMEM>>>(pq, pk, attn);

    // --- chain B (stream sB): FF1 -> FF2 ---
    dim3 g0(Dd / 128, NTOK / 128);
    gemm_ca<1, false><<<g0, 256, GA_SMEM, sB>>>(ph2, pw1, nullptr,
                                                nullptr, ff1b, nullptr,
                                                pf1, nullptr);
    gemm_ca<2, false><<<g0, 256, GA_SMEM, sB>>>(pf1, pw2, nullptr,
                                                out, ff2b, px2,
                                                nullptr, nullptr);

    // join: stream 0 waits for chain B before kernel_launch returns
    cudaEventRecord(evJoin, sB);
    cudaStreamWaitEvent(0, evJoin, 0);
}

// round 17
// speedup vs baseline: 1.0765x; 1.0765x over previous
#include <cuda_runtime.h>
#include <cuda_fp16.h>
#include <cstdint>
#include <math.h>

#define Dd    2048
#define NTOK  4096
#define Sq    1024
#define HDh   64
#define NBH   128
#define EPSV  1e-5f
#define INV_SQRT_D 0.022097086912079608f

// ---------------- scratch ---------------------------------------------------
__device__ float g_x2[(size_t)NTOK * Dd];
__device__ __half g_h [(size_t)NTOK * Dd];
__device__ __half g_h2[(size_t)NTOK * Dd];
__device__ __half g_f1[(size_t)NTOK * Dd];
__device__ __half g_q[(size_t)NTOK * Dd], g_k[(size_t)NTOK * Dd];
__device__ __half g_wq[(size_t)Dd * Dd], g_wk[(size_t)Dd * Dd];
__device__ __half g_w1[(size_t)Dd * Dd], g_w2[(size_t)Dd * Dd];

// ---------------- helpers ----------------------------------------------------
__device__ __forceinline__ uint32_t smem_u32(const void* p) {
    return (uint32_t)__cvta_generic_to_shared(p);
}
__device__ __forceinline__ void cp16(uint32_t dst, const void* src) {
    asm volatile("cp.async.cg.shared.global [%0], [%1], 16;" :: "r"(dst), "l"(src));
}
__device__ __forceinline__ void cp_commit() {
    asm volatile("cp.async.commit_group;");
}
template<int N> __device__ __forceinline__ void cp_wait() {
    asm volatile("cp.async.wait_group %0;" :: "n"(N));
}
__device__ __forceinline__ void ldmx4(uint32_t a, uint32_t& r0, uint32_t& r1,
                                      uint32_t& r2, uint32_t& r3) {
    asm volatile("ldmatrix.sync.aligned.m8n8.x4.shared.b16 {%0,%1,%2,%3},[%4];"
                 : "=r"(r0), "=r"(r1), "=r"(r2), "=r"(r3) : "r"(a));
}
__device__ __forceinline__ void ldmx4t(uint32_t a, uint32_t& r0, uint32_t& r1,
                                       uint32_t& r2, uint32_t& r3) {
    asm volatile("ldmatrix.sync.aligned.m8n8.x4.trans.shared.b16 {%0,%1,%2,%3},[%4];"
                 : "=r"(r0), "=r"(r1), "=r"(r2), "=r"(r3) : "r"(a));
}
__device__ __forceinline__ void mma16816(float* c, const uint32_t* a, const uint32_t* b) {
    asm volatile(
        "mma.sync.aligned.m16n8k16.row.col.f32.f16.f16.f32 "
        "{%0,%1,%2,%3},{%4,%5,%6,%7},{%8,%9},{%0,%1,%2,%3};"
        : "+f"(c[0]), "+f"(c[1]), "+f"(c[2]), "+f"(c[3])
        : "r"(a[0]), "r"(a[1]), "r"(a[2]), "r"(a[3]), "r"(b[0]), "r"(b[1]));
}

// ---------------- all-weights convert (one launch) ----------------------------
struct CvtArgs {
    const float4* w[4];
    __half* o[4];
};
__global__ __launch_bounds__(256) void cvt_all(CvtArgs a, int n4) {
    const int z = blockIdx.y;
    const float4* W = a.w[z];
    __half* o = a.o[z];
    int i = blockIdx.x * 256 + threadIdx.x;
    if (i >= n4) return;
    float4 v = W[i];
    *(__half2*)(o + (size_t)i * 4)     = __floats2half2_rn(v.x, v.y);
    *(__half2*)(o + (size_t)i * 4 + 2) = __floats2half2_rn(v.z, v.w);
}

// ---------------- fused LN1 / residual / LN2 (single-plane fp16 outputs) ------
__global__ __launch_bounds__(256) void ln_fused(
    const float* __restrict__ x,
    const float* __restrict__ s1, const float* __restrict__ b1,
    const float* __restrict__ s2, const float* __restrict__ b2)
{
    __shared__ float rbuf[16];
    __shared__ float stats[2];
    const int tid = threadIdx.x;
    const size_t base = (size_t)blockIdx.x * Dd;
    const float4* xr = (const float4*)(x + base);
    float4 a0 = xr[tid];
    float4 a1 = xr[tid + 256];

    float s = a0.x + a0.y + a0.z + a0.w + a1.x + a1.y + a1.z + a1.w;
    float q = a0.x*a0.x + a0.y*a0.y + a0.z*a0.z + a0.w*a0.w
            + a1.x*a1.x + a1.y*a1.y + a1.z*a1.z + a1.w*a1.w;
    #pragma unroll
    for (int o = 16; o; o >>= 1) {
        s += __shfl_xor_sync(0xffffffffu, s, o);
        q += __shfl_xor_sync(0xffffffffu, q, o);
    }
    if ((tid & 31) == 0) { rbuf[tid >> 5] = s; rbuf[8 + (tid >> 5)] = q; }
    __syncthreads();
    if (tid == 0) {
        float ss = 0.f, qq = 0.f;
        #pragma unroll
        for (int i = 0; i < 8; i++) { ss += rbuf[i]; qq += rbuf[8 + i]; }
        float m = ss * (1.0f / Dd);
        stats[0] = m;
        stats[1] = rsqrtf(qq * (1.0f / Dd) - m * m + EPSV);
    }
    __syncthreads();
    float m = stats[0], r = stats[1];

    const float4* s1v = (const float4*)s1;
    const float4* b1v = (const float4*)b1;
    float4 sc0 = s1v[tid], sc1 = s1v[tid + 256];
    float4 bi0 = b1v[tid], bi1 = b1v[tid + 256];

    float4 h0, h1, x20, x21;
    h0.x = (a0.x - m) * r * sc0.x + bi0.x;  h0.y = (a0.y - m) * r * sc0.y + bi0.y;
    h0.z = (a0.z - m) * r * sc0.z + bi0.z;  h0.w = (a0.w - m) * r * sc0.w + bi0.w;
    h1.x = (a1.x - m) * r * sc1.x + bi1.x;  h1.y = (a1.y - m) * r * sc1.y + bi1.y;
    h1.z = (a1.z - m) * r * sc1.z + bi1.z;  h1.w = (a1.w - m) * r * sc1.w + bi1.w;
    x20.x = h0.x + a0.x; x20.y = h0.y + a0.y; x20.z = h0.z + a0.z; x20.w = h0.w + a0.w;
    x21.x = h1.x + a1.x; x21.y = h1.y + a1.y; x21.z = h1.z + a1.z; x21.w = h1.w + a1.w;

    *(__half2*)(g_h + base + (size_t)tid * 4)       = __floats2half2_rn(h0.x, h0.y);
    *(__half2*)(g_h + base + (size_t)tid * 4 + 2)   = __floats2half2_rn(h0.z, h0.w);
    *(__half2*)(g_h + base + (size_t)(tid + 256) * 4)     = __floats2half2_rn(h1.x, h1.y);
    *(__half2*)(g_h + base + (size_t)(tid + 256) * 4 + 2) = __floats2half2_rn(h1.z, h1.w);
    ((float4*)(g_x2 + base))[tid]       = x20;
    ((float4*)(g_x2 + base))[tid + 256] = x21;

    s = x20.x + x20.y + x20.z + x20.w + x21.x + x21.y + x21.z + x21.w;
    q = x20.x*x20.x + x20.y*x20.y + x20.z*x20.z + x20.w*x20.w
      + x21.x*x21.x + x21.y*x21.y + x21.z*x21.z + x21.w*x21.w;
    #pragma unroll
    for (int o = 16; o; o >>= 1) {
        s += __shfl_xor_sync(0xffffffffu, s, o);
        q += __shfl_xor_sync(0xffffffffu, q, o);
    }
    if ((tid & 31) == 0) { rbuf[tid >> 5] = s; rbuf[8 + (tid >> 5)] = q; }
    __syncthreads();
    if (tid == 0) {
        float ss = 0.f, qq = 0.f;
        #pragma unroll
        for (int i = 0; i < 8; i++) { ss += rbuf[i]; qq += rbuf[8 + i]; }
        float mm = ss * (1.0f / Dd);
        stats[0] = mm;
        stats[1] = rsqrtf(qq * (1.0f / Dd) - mm * mm + EPSV);
    }
    __syncthreads();
    m = stats[0]; r = stats[1];

    const float4* s2v = (const float4*)s2;
    const float4* b2v = (const float4*)b2;
    sc0 = s2v[tid]; sc1 = s2v[tid + 256];
    bi0 = b2v[tid]; bi1 = b2v[tid + 256];
    float4 o0, o1;
    o0.x = (x20.x - m) * r * sc0.x + bi0.x;  o0.y = (x20.y - m) * r * sc0.y + bi0.y;
    o0.z = (x20.z - m) * r * sc0.z + bi0.z;  o0.w = (x20.w - m) * r * sc0.w + bi0.w;
    o1.x = (x21.x - m) * r * sc1.x + bi1.x;  o1.y = (x21.y - m) * r * sc1.y + bi1.y;
    o1.z = (x21.z - m) * r * sc1.z + bi1.z;  o1.w = (x21.w - m) * r * sc1.w + bi1.w;
    *(__half2*)(g_h2 + base + (size_t)tid * 4)       = __floats2half2_rn(o0.x, o0.y);
    *(__half2*)(g_h2 + base + (size_t)tid * 4 + 2)   = __floats2half2_rn(o0.z, o0.w);
    *(__half2*)(g_h2 + base + (size_t)(tid + 256) * 4)     = __floats2half2_rn(o1.x, o1.y);
    *(__half2*)(g_h2 + base + (size_t)(tid + 256) * 4 + 2) = __floats2half2_rn(o1.z, o1.w);
}

// ---------------------------------------------------------------------------
// Pure fp16 GEMM, cp.async 3-stage ring, BK=64 (R15, kept).
// ---------------------------------------------------------------------------
#define GA_B     18432u
#define GA_STAGE 35840u
#define GA_SMEM  107520u
#define GA_ITERS (Dd / 64)

template<int EPI, bool DUAL>
__global__ __launch_bounds__(256, 2) void gemm_ca(
    const __half* __restrict__ Am,
    const __half* __restrict__ Bm, const __half* __restrict__ Bm2,
    float* __restrict__ C,
    const float* __restrict__ bias, const float* __restrict__ addm,
    __half* __restrict__ O, __half* __restrict__ O2)
{
    extern __shared__ __align__(16) char dsm[];
    const uint32_t sb = smem_u32(dsm);
    const int N = Dd, K = Dd;

    const __half* Bsel = Bm;
    __half* Osel = O;
    if (DUAL && blockIdx.z == 1) { Bsel = Bm2; Osel = O2; }

    const int tid = threadIdx.x;
    const int m0 = blockIdx.y * 128, n0 = blockIdx.x * 128;

    auto ISSUE = [&](int ch, int stage) {
        uint32_t st = sb + (uint32_t)stage * GA_STAGE;
        const int kof = ch * 64;
        #pragma unroll
        for (int p = 0; p < 4; p++) {
            int idx = tid + p * 256;
            int ar = idx >> 3, ac = (idx & 7) * 8;
            cp16(st + (uint32_t)(ar * 72 + ac) * 2,
                 Am + (size_t)(m0 + ar) * K + kof + ac);
            int br = idx >> 4, bc = (idx & 15) * 8;
            cp16(st + GA_B + (uint32_t)(br * 136 + bc) * 2,
                 Bsel + (size_t)(kof + br) * N + n0 + bc);
        }
        cp_commit();
    };

    const int lane = tid & 31;
    const int wid = tid >> 5;
    const int wm = (wid & 1) * 64;
    const int wn = (wid >> 1) * 32;
    const uint32_t aRow = (uint32_t)((wm + (lane & 15)) * 72 + ((lane >> 4) << 3)) * 2;
    const uint32_t bRow = (uint32_t)((lane & 15) * 136 + wn + ((lane >> 4) << 3)) * 2;

    float acc[4][4][4];
    #pragma unroll
    for (int i = 0; i < 4; i++)
        #pragma unroll
        for (int j = 0; j < 4; j++)
            #pragma unroll
            for (int t = 0; t < 4; t++) acc[i][j][t] = 0.f;

    auto COMP = [&](int stage) {
        const uint32_t aB = sb + (uint32_t)stage * GA_STAGE + aRow;
        const uint32_t bB = sb + (uint32_t)stage * GA_STAGE + GA_B + bRow;
        #pragma unroll
        for (int kb = 0; kb < 64; kb += 16) {
            uint32_t bf[4][2];
            #pragma unroll
            for (int np = 0; np < 2; np++) {
                ldmx4t(bB + ((kb * 136 + np * 16) << 1),
                       bf[2*np][0], bf[2*np][1], bf[2*np+1][0], bf[2*np+1][1]);
            }
            #pragma unroll
            for (int mt = 0; mt < 4; mt++) {
                uint32_t af[4];
                ldmx4(aB + ((mt * 16 * 72 + kb) << 1),
                      af[0], af[1], af[2], af[3]);
                #pragma unroll
                for (int nt = 0; nt < 4; nt++)
                    mma16816(acc[mt][nt], af, bf[nt]);
            }
        }
    };

    ISSUE(0, 0);
    ISSUE(1, 1);
    for (int it = 0; it < GA_ITERS; it++) {
        if (it == GA_ITERS - 1) cp_wait<0>(); else cp_wait<1>();
        __syncthreads();
        if (it + 2 < GA_ITERS) ISSUE(it + 2, (it + 2) % 3);
        COMP(it % 3);
    }

    const int g = lane >> 2, tig = lane & 3;
    #pragma unroll
    for (int mt = 0; mt < 4; mt++) {
        #pragma unroll
        for (int nt = 0; nt < 4; nt++) {
            const int row = m0 + wm + mt * 16 + g;
            const int col = n0 + wn + nt * 8 + tig * 2;
            const float* a4 = acc[mt][nt];
            if (EPI == 4) {
                *(__half2*)(Osel + (size_t)row * N + col) =
                    __floats2half2_rn(a4[0], a4[1]);
                *(__half2*)(Osel + (size_t)(row + 8) * N + col) =
                    __floats2half2_rn(a4[2], a4[3]);
            } else if (EPI == 1) {
                float b0 = bias[col], b1 = bias[col + 1];
                *(__half2*)(O + (size_t)row * N + col) =
                    __floats2half2_rn(fmaxf(a4[0] + b0, 0.f), fmaxf(a4[1] + b1, 0.f));
                *(__half2*)(O + (size_t)(row + 8) * N + col) =
                    __floats2half2_rn(fmaxf(a4[2] + b0, 0.f), fmaxf(a4[3] + b1, 0.f));
            } else { // EPI == 2
                float b0 = bias[col], b1 = bias[col + 1];
                float2 ad0 = *(const float2*)(addm + (size_t)row * N + col);
                float2 ad1 = *(const float2*)(addm + (size_t)(row + 8) * N + col);
                *(float2*)(C + (size_t)row * N + col) =
                    make_float2(a4[0] + b0 + ad0.x, a4[1] + b1 + ad0.y);
                *(float2*)(C + (size_t)(row + 8) * N + col) =
                    make_float2(a4[2] + b0 + ad1.x, a4[3] + b1 + ad1.y);
            }
        }
    }
}

// -----------------------------------------------------------------------------
// Fused scores + softmax — single-plane fp16 q/k; bhOff selects batch-head range.
// -----------------------------------------------------------------------------
#define FS_Q    0u
#define FS_K0   2304u
#define FS_KBUF 36864u
#define FS_RED  76032u
#define FS_SMEM 77056u

__global__ __launch_bounds__(512) void scores_softmax(
    const __half* __restrict__ Q, const __half* __restrict__ Kk,
    float* __restrict__ attn, int bhOff)
{
    extern __shared__ __align__(16) char dsm[];
    const uint32_t sbase = smem_u32(dsm);
    float* red = (float*)(dsm + FS_RED);

    const int tid = threadIdx.x;
    const int lane = tid & 31;
    const int wid = tid >> 5;
    const int bh = blockIdx.y + bhOff;
    const int m0 = blockIdx.x * 16;
    const size_t off = (size_t)(bh >> 5) * ((size_t)Sq * Dd) + (size_t)(bh & 31) * HDh;

    if (tid < 128) {
        int row = tid >> 3, col = (tid & 7) * 8;
        cp16(sbase + FS_Q + (row * 72 + col) * 2,
             Q + off + (size_t)(m0 + row) * Dd + col);
    }
    auto ISSUEK = [&](int chunk, int buf) {
        #pragma unroll
        for (int p = 0; p < 4; p++) {
            int idx = tid + p * 512;
            int row = idx >> 3, col = (idx & 7) * 8;
            cp16(sbase + FS_K0 + (uint32_t)buf * FS_KBUF + (row * 72 + col) * 2,
                 Kk + off + (size_t)(chunk * 256 + row) * Dd + col);
        }
        cp_commit();
    };
    ISSUEK(0, 0);
    ISSUEK(1, 1);
    cp_wait<1>();
    __syncthreads();

    const uint32_t aOff = (((lane & 15)) * 72 + ((lane >> 4) << 3)) * 2;
    uint32_t af[4][4];
    #pragma unroll
    for (int kb4 = 0; kb4 < 4; kb4++) {
        ldmx4(sbase + FS_Q + aOff + ((kb4 * 16) << 1),
              af[kb4][0], af[kb4][1], af[kb4][2], af[kb4][3]);
    }

    const int bRow = ((lane >> 4) << 3) + (lane & 7);
    const int bKof = ((lane >> 3) & 1) << 3;
    const uint32_t bOff = ((wid * 16 + bRow) * 72 + bKof) * 2;

    float acc[4][2][4];
    #pragma unroll
    for (int it = 0; it < 4; it++)
        #pragma unroll
        for (int nt = 0; nt < 2; nt++)
            #pragma unroll
            for (int t = 0; t < 4; t++) acc[it][nt][t] = 0.f;

    #pragma unroll
    for (int it = 0; it < 4; it++) {
        const int buf = it & 1;
        const uint32_t kb = sbase + FS_K0 + (uint32_t)buf * FS_KBUF + bOff;
        #pragma unroll
        for (int kb4 = 0; kb4 < 4; kb4++) {
            uint32_t b4[4];
            ldmx4(kb + ((kb4 * 16) << 1), b4[0], b4[1], b4[2], b4[3]);
            mma16816(acc[it][0], af[kb4], &b4[0]);
            mma16816(acc[it][1], af[kb4], &b4[2]);
        }
        if (it < 2) {
            __syncthreads();
            ISSUEK(it + 2, buf);
            cp_wait<1>();
            __syncthreads();
        } else if (it == 2) {
            cp_wait<0>();
            __syncthreads();
        }
    }

    const int g = lane >> 2, tig = lane & 3;
    const float c = INV_SQRT_D;
    float mx0 = -1e30f, mx1 = -1e30f;
    #pragma unroll
    for (int it = 0; it < 4; it++)
        #pragma unroll
        for (int nt = 0; nt < 2; nt++) {
            float* a4 = acc[it][nt];
            a4[0] *= c; a4[1] *= c; a4[2] *= c; a4[3] *= c;
            mx0 = fmaxf(mx0, fmaxf(a4[0], a4[1]));
            mx1 = fmaxf(mx1, fmaxf(a4[2], a4[3]));
        }
    mx0 = fmaxf(mx0, __shfl_xor_sync(0xffffffffu, mx0, 1));
    mx0 = fmaxf(mx0, __shfl_xor_sync(0xffffffffu, mx0, 2));
    mx1 = fmaxf(mx1, __shfl_xor_sync(0xffffffffu, mx1, 1));
    mx1 = fmaxf(mx1, __shfl_xor_sync(0xffffffffu, mx1, 2));
    if (tig == 0) { red[g * 16 + wid] = mx0; red[(g + 8) * 16 + wid] = mx1; }
    __syncthreads();
    float m0f = -1e30f, m1f = -1e30f;
    #pragma unroll
    for (int w = 0; w < 16; w++) {
        m0f = fmaxf(m0f, red[g * 16 + w]);
        m1f = fmaxf(m1f, red[(g + 8) * 16 + w]);
    }
    __syncthreads();

    float s0 = 0.f, s1 = 0.f;
    #pragma unroll
    for (int it = 0; it < 4; it++)
        #pragma unroll
        for (int nt = 0; nt < 2; nt++) {
            float* a4 = acc[it][nt];
            a4[0] = __expf(a4[0] - m0f); a4[1] = __expf(a4[1] - m0f);
            a4[2] = __expf(a4[2] - m1f); a4[3] = __expf(a4[3] - m1f);
            s0 += a4[0] + a4[1];
            s1 += a4[2] + a4[3];
        }
    s0 += __shfl_xor_sync(0xffffffffu, s0, 1);
    s0 += __shfl_xor_sync(0xffffffffu, s0, 2);
    s1 += __shfl_xor_sync(0xffffffffu, s1, 1);
    s1 += __shfl_xor_sync(0xffffffffu, s1, 2);
    if (tig == 0) { red[g * 16 + wid] = s0; red[(g + 8) * 16 + wid] = s1; }
    __syncthreads();
    float t0 = 0.f, t1 = 0.f;
    #pragma unroll
    for (int w = 0; w < 16; w++) {
        t0 += red[g * 16 + w];
        t1 += red[(g + 8) * 16 + w];
    }
    const float inv0 = __fdividef(1.0f, t0);
    const float inv1 = __fdividef(1.0f, t1);

    float* base0 = attn + (size_t)bh * Sq * Sq + (size_t)(m0 + g) * Sq;
    float* base1 = base0 + (size_t)8 * Sq;
    #pragma unroll
    for (int it = 0; it < 4; it++)
        #pragma unroll
        for (int nt = 0; nt < 2; nt++) {
            const int col = it * 256 + wid * 16 + nt * 8 + tig * 2;
            const float* a4 = acc[it][nt];
            *(float2*)(base0 + col) = make_float2(a4[0] * inv0, a4[1] * inv0);
            *(float2*)(base1 + col) = make_float2(a4[2] * inv1, a4[3] * inv1);
        }
}

// -----------------------------------------------------------------------------
extern "C" void kernel_launch(void* const* d_in, const int* in_sizes, int n_in,
                              void* d_out, int out_size)
{
    (void)in_sizes; (void)n_in; (void)out_size;
    const float* x    = (const float*)d_in[0];
    const float* Wq   = (const float*)d_in[1];
    const float* Wk   = (const float*)d_in[2];
    /* d_in[3] = Wv : dead in the reference */
    const float* ln1s = (const float*)d_in[4];
    const float* ln1b = (const float*)d_in[5];
    const float* ln2s = (const float*)d_in[6];
    const float* ln2b = (const float*)d_in[7];
    const float* ff1w = (const float*)d_in[8];
    const float* ff1b = (const float*)d_in[9];
    const float* ff2w = (const float*)d_in[10];
    const float* ff2b = (const float*)d_in[11];

    float* out  = (float*)d_out;
    float* attn = out + (size_t)NTOK * Dd;

    float* px2;
    __half *ph, *ph2, *pf1, *pq, *pk;
    __half *pwq, *pwk, *pw1, *pw2;
    cudaGetSymbolAddress((void**)&px2, g_x2);
    cudaGetSymbolAddress((void**)&ph,  g_h);
    cudaGetSymbolAddress((void**)&ph2, g_h2);
    cudaGetSymbolAddress((void**)&pf1, g_f1);
    cudaGetSymbolAddress((void**)&pq,  g_q);
    cudaGetSymbolAddress((void**)&pk,  g_k);
    cudaGetSymbolAddress((void**)&pwq, g_wq);
    cudaGetSymbolAddress((void**)&pwk, g_wk);
    cudaGetSymbolAddress((void**)&pw1, g_w1);
    cudaGetSymbolAddress((void**)&pw2, g_w2);

    cudaFuncSetAttribute(gemm_ca<4, true>,
                         cudaFuncAttributeMaxDynamicSharedMemorySize, GA_SMEM);
    cudaFuncSetAttribute(gemm_ca<1, false>,
                         cudaFuncAttributeMaxDynamicSharedMemorySize, GA_SMEM);
    cudaFuncSetAttribute(gemm_ca<2, false>,
                         cudaFuncAttributeMaxDynamicSharedMemorySize, GA_SMEM);
    cudaFuncSetAttribute(scores_softmax,
                         cudaFuncAttributeMaxDynamicSharedMemorySize, FS_SMEM);

    // Streams/events: host-side objects, created once.
    //   sB (lowest prio): FFN chain, forked right after the prologue (R15 best).
    //   sC (highest prio): scores halves, released per qk-projection half.
    static cudaStream_t sB = nullptr, sC = nullptr;
    static cudaEvent_t evFork = nullptr, evH1 = nullptr, evH2 = nullptr;
    static cudaEvent_t evJoinB = nullptr, evJoinC = nullptr;
    if (sB == nullptr) {
        int prLeast = 0, prGreatest = 0;
        cudaDeviceGetStreamPriorityRange(&prLeast, &prGreatest);
        cudaStreamCreateWithPriority(&sB, cudaStreamNonBlocking, prLeast);
        cudaStreamCreateWithPriority(&sC, cudaStreamNonBlocking, prGreatest);
        cudaEventCreateWithFlags(&evFork,  cudaEventDisableTiming);
        cudaEventCreateWithFlags(&evH1,    cudaEventDisableTiming);
        cudaEventCreateWithFlags(&evH2,    cudaEventDisableTiming);
        cudaEventCreateWithFlags(&evJoinB, cudaEventDisableTiming);
        cudaEventCreateWithFlags(&evJoinC, cudaEventDisableTiming);
    }

    // --- stream 0: ln + cvt (shared prologue) ---
    ln_fused<<<NTOK, 256>>>(x, ln1s, ln1b, ln2s, ln2b);

    CvtArgs ca;
    ca.w[0] = (const float4*)Wq;   ca.o[0] = pwq;
    ca.w[1] = (const float4*)Wk;   ca.o[1] = pwk;
    ca.w[2] = (const float4*)ff1w; ca.o[2] = pw1;
    ca.w[3] = (const float4*)ff2w; ca.o[3] = pw2;
    const int n4 = Dd * Dd / 4;
    dim3 gc((n4 + 255) / 256, 4);
    cvt_all<<<gc, 256>>>(ca, n4);

    // fork FFN immediately after prologue (R15's winning position)
    cudaEventRecord(evFork, 0);
    cudaStreamWaitEvent(sB, evFork, 0);
    dim3 g0(Dd / 128, NTOK / 128);
    gemm_ca<1, false><<<g0, 256, GA_SMEM, sB>>>(ph2, pw1, nullptr,
                                                nullptr, ff1b, nullptr,
                                                pf1, nullptr);
    gemm_ca<2, false><<<g0, 256, GA_SMEM, sB>>>(pf1, pw2, nullptr,
                                                out, ff2b, px2,
                                                nullptr, nullptr);

    // --- stream 0: qk projection in two M-halves ---
    const size_t halfOff = (size_t)(NTOK / 2) * Dd;   // rows 2048.. (row-major)
    dim3 gqkh(Dd / 128, (NTOK / 2) / 128, 2);
    gemm_ca<4, true><<<gqkh, 256, GA_SMEM>>>(ph, pwq, pwk,
                                             nullptr, nullptr, nullptr,
                                             pq, pk);
    cudaEventRecord(evH1, 0);
    gemm_ca<4, true><<<gqkh, 256, GA_SMEM>>>(ph + halfOff, pwq, pwk,
                                             nullptr, nullptr, nullptr,
                                             pq + halfOff, pk + halfOff);
    cudaEventRecord(evH2, 0);

    // --- stream sC: scores halves, released as soon as their q/k are ready ---
    dim3 gsh(Sq / 16, NBH / 2);
    cudaStreamWaitEvent(sC, evH1, 0);
    scores_softmax<<<gsh, 512, FS_SMEM, sC>>>(pq, pk, attn, 0);
    cudaStreamWaitEvent(sC, evH2, 0);
    scores_softmax<<<gsh, 512, FS_SMEM, sC>>>(pq, pk, attn, NBH / 2);

    // join both side chains into stream 0
    cudaEventRecord(evJoinB, sB);
    cudaStreamWaitEvent(0, evJoinB, 0);
    cudaEventRecord(evJoinC, sC);
    cudaStreamWaitEvent(0, evJoinC, 0);
}